// round 4
// baseline (speedup 1.0000x reference)
#include <cuda_runtime.h>
#include <cuda_bf16.h>
#include <math.h>

// Problem constants (fixed by the reference)
#define NPSD   256          // L*D = flat node repr dim
#define SINT   32           // intersection set size
#define RELD_  32
#define INPF   32           // node_feat dim
#define DD     64           // dist emb dim
#define GDIM   864          // g_rep dim: 256+256+32+256+32+32

#define LPB    8            // links per block
#define NTHR   256

// shared layout (floats):
//  sg    : LPB*GDIM = 6912
//  sdist : LPB*64   = 512
//  sh1   : LPB*64   = 512
//  sh2   : LPB*32   = 256
//  red   : 8*8*64   = 4096   (red[q*512 + l*64 + j]) - reused pred then W1
//  ints  : sidx LPB*S=256, shead/stail/srel/sdi 4*LPB=32
#define SMEM_FLOATS (LPB*GDIM + LPB*64 + LPB*64 + LPB*32 + 8*LPB*64)
#define SMEM_INTS   (LPB*SINT + 4*LPB)
#define SMEM_BYTES  ((SMEM_FLOATS + SMEM_INTS) * 4)

__global__ void __launch_bounds__(NTHR, 4) gcw_fused(
    const float* __restrict__ flat,      // [N, 256]
    const float* __restrict__ feat,      // [N, 32]
    const int*   __restrict__ head_idx,  // [B]
    const int*   __restrict__ rel_idx,   // [B]
    const int*   __restrict__ tail_idx,  // [B]
    const int*   __restrict__ dist_idx,  // [B]
    const int*   __restrict__ inter,     // [B, 32]
    const float* __restrict__ rel_emb,   // [200, 32]
    const float* __restrict__ dist_emb,  // [11, 64]
    const float* __restrict__ headW,     // [320, 32]
    const float* __restrict__ headb,     // [32]
    const float* __restrict__ tailW,     // [320, 32]
    const float* __restrict__ tailb,     // [32]
    const float* __restrict__ W1,        // [864, 64]
    const float* __restrict__ b1,        // [64]
    const float* __restrict__ W2,        // [64, 32]
    const float* __restrict__ b2,        // [32]
    const float* __restrict__ W3,        // [32, 1]
    const float* __restrict__ b3,        // [1]
    float* __restrict__ out, int B)
{
    extern __shared__ float sh[];
    float* sg    = sh;                          // [LPB][GDIM]
    float* sdist = sg    + LPB * GDIM;          // [LPB][64]
    float* sh1   = sdist + LPB * 64;            // [LPB][64]
    float* sh2   = sh1   + LPB * 64;            // [LPB][32]
    float* red   = sh2   + LPB * 32;            // [8][LPB][64]
    int*   sidx  = (int*)(red + 8 * LPB * 64);  // [LPB][S]
    int*   shead = sidx  + LPB * SINT;
    int*   stail = shead + LPB;
    int*   srel  = stail + LPB;
    int*   sdi   = srel  + LPB;

    const int t  = threadIdx.x;
    const int b0 = blockIdx.x * LPB;

    // ---- load per-link indices ----
    if (t < LPB) {
        int b = min(b0 + t, B - 1);
        shead[t] = head_idx[b];
        stail[t] = tail_idx[b];
        srel[t]  = rel_idx[b];
        sdi[t]   = dist_idx[b];
    }
    {
        int gi = min(b0 * SINT + t, B * SINT - 1);   // LPB*SINT == NTHR
        sidx[t] = inter[gi];
    }
    __syncthreads();

    const int g  = t >> 6;          // 0..3
    const int c4 = (t & 63) * 4;    // float4 column base within 256

    // ---- gather head/tail reprs (float4, streaming: no L1 reuse) ----
    #pragma unroll
    for (int li = 0; li < 2; li++) {
        int l = g + li * 4;
        float4 h  = __ldcs((const float4*)&flat[(long)shead[l] * NPSD + c4]);
        float4 tl = __ldcs((const float4*)&flat[(long)stail[l] * NPSD + c4]);
        *(float4*)&sg[l * GDIM + c4]       = h;
        *(float4*)&sg[l * GDIM + 256 + c4] = tl;
    }
    // rel_repr, head/tail feats  (LPB*32 == NTHR)
    {
        int l = t >> 5, j = t & 31;
        sg[l * GDIM + 512 + j] = rel_emb[(long)srel[l] * RELD_ + j];
        sg[l * GDIM + 800 + j] = feat[(long)shead[l] * INPF + j];
        sg[l * GDIM + 832 + j] = feat[(long)stail[l] * INPF + j];
    }
    // dist_repr (LPB*64 = 512 -> 2 reps)
    #pragma unroll
    for (int rep = 0; rep < 2; rep++) {
        int u = rep * NTHR + t;
        int l = u >> 6, j = u & 63;
        sdist[l * 64 + j] = dist_emb[(long)sdi[l] * DD + j];
    }

    // ---- mid: masked-mean gather, float4 per thread, streaming ----
    #pragma unroll
    for (int li = 0; li < 2; li++) {
        int l = g + li * 4;
        float4 a0 = make_float4(0.f, 0.f, 0.f, 0.f);
        float4 a1 = make_float4(0.f, 0.f, 0.f, 0.f);
        int cnt = 0;
        #pragma unroll 4
        for (int s = 0; s < SINT; s += 2) {
            int i0 = sidx[l * SINT + s];
            int i1 = sidx[l * SINT + s + 1];
            int a0i = i0 < 0 ? -i0 : i0;
            int a1i = i1 < 0 ? -i1 : i1;
            float s0 = (float)((i0 > -1) - (i0 < -1));
            float s1 = (float)((i1 > -1) - (i1 < -1));
            cnt += (i0 != -1) + (i1 != -1);
            const float4 v0 = __ldcs((const float4*)&flat[(long)a0i * NPSD + c4]);
            const float4 v1 = __ldcs((const float4*)&flat[(long)a1i * NPSD + c4]);
            a0.x = fmaf(v0.x, s0, a0.x);
            a0.y = fmaf(v0.y, s0, a0.y);
            a0.z = fmaf(v0.z, s0, a0.z);
            a0.w = fmaf(v0.w, s0, a0.w);
            a1.x = fmaf(v1.x, s1, a1.x);
            a1.y = fmaf(v1.y, s1, a1.y);
            a1.z = fmaf(v1.z, s1, a1.z);
            a1.w = fmaf(v1.w, s1, a1.w);
        }
        float inv = 1.f / (float)max(cnt, 1);
        float4 r;
        r.x = (a0.x + a1.x) * inv;
        r.y = (a0.y + a1.y) * inv;
        r.z = (a0.z + a1.z) * inv;
        r.w = (a0.w + a1.w) * inv;
        *(float4*)&sg[l * GDIM + 544 + c4] = r;
    }

    // ---- emit head/tail init feats (LPB*32 == NTHR) ----
    {
        long hf = (long)B + 2L * B * 32;
        long tf = (long)B + 3L * B * 32;
        int l = t >> 5, j = t & 31;
        int b = b0 + l;
        if (b < B) {
            out[hf + (long)b * 32 + j] = feat[(long)shead[l] * INPF + j];
            out[tf + (long)b * 32 + j] = feat[(long)stail[l] * INPF + j];
        }
    }
    __syncthreads();

    // ---- head/tail pred: md[320] @ W[320,32], jtile=2, 8-way split-K ----
    {
        const int jj2 = (t & 15) * 2;        // 0,2,...,30
        const int sel = (t >> 4) & 1;        // 0=head, 1=tail
        const int q   = t >> 5;              // 0..7
        const float* W = sel ? tailW : headW;
        float acc[LPB][2];
        #pragma unroll
        for (int l = 0; l < LPB; l++) { acc[l][0] = 0.f; acc[l][1] = 0.f; }

        const int k0 = q * 40;
        #pragma unroll 2
        for (int k = k0; k < k0 + 40; k += 4) {
            float2 w0 = *(const float2*)&W[(k    ) * INPF + jj2];
            float2 w1 = *(const float2*)&W[(k + 1) * INPF + jj2];
            float2 w2 = *(const float2*)&W[(k + 2) * INPF + jj2];
            float2 w3 = *(const float2*)&W[(k + 3) * INPF + jj2];
            #pragma unroll
            for (int l = 0; l < LPB; l++) {
                float4 m;
                if (k < 256) m = *(const float4*)&sg[l * GDIM + 544 + k];
                else         m = *(const float4*)&sdist[l * 64 + (k - 256)];
                acc[l][0] = fmaf(m.x, w0.x, acc[l][0]);
                acc[l][1] = fmaf(m.x, w0.y, acc[l][1]);
                acc[l][0] = fmaf(m.y, w1.x, acc[l][0]);
                acc[l][1] = fmaf(m.y, w1.y, acc[l][1]);
                acc[l][0] = fmaf(m.z, w2.x, acc[l][0]);
                acc[l][1] = fmaf(m.z, w2.y, acc[l][1]);
                acc[l][0] = fmaf(m.w, w3.x, acc[l][0]);
                acc[l][1] = fmaf(m.w, w3.y, acc[l][1]);
            }
        }
        #pragma unroll
        for (int l = 0; l < LPB; l++)
            *(float2*)&red[q * 512 + l * 64 + sel * 32 + jj2] =
                make_float2(acc[l][0], acc[l][1]);
    }
    __syncthreads();

    // ---- reduce pred partials + bias -> out ----
    #pragma unroll
    for (int rep = 0; rep < 2; rep++) {
        int p = rep * NTHR + t;
        int l = p >> 6, j = p & 63, jj = j & 31;
        float s = 0.f;
        #pragma unroll
        for (int q = 0; q < 8; q++) s += red[q * 512 + l * 64 + j];
        int b = b0 + l;
        if (b < B) {
            if (j < 32) out[B + (long)b * 32 + jj] = s + headb[jj];
            else        out[B + (long)B * 32 + (long)b * 32 + jj] = s + tailb[jj];
        }
    }
    __syncthreads();   // red reused below

    // ---- W1: g_rep[864] @ W1[864,64], jtile=2, 8-way split-K ----
    {
        const int j2 = (t & 31) * 2;         // 0,2,...,62
        const int q  = t >> 5;               // 0..7
        float acc[LPB][2];
        #pragma unroll
        for (int l = 0; l < LPB; l++) { acc[l][0] = 0.f; acc[l][1] = 0.f; }

        const int k0 = q * 108;
        #pragma unroll 3
        for (int k = k0; k < k0 + 108; k += 4) {
            float2 w0 = *(const float2*)&W1[(k    ) * 64 + j2];
            float2 w1 = *(const float2*)&W1[(k + 1) * 64 + j2];
            float2 w2 = *(const float2*)&W1[(k + 2) * 64 + j2];
            float2 w3 = *(const float2*)&W1[(k + 3) * 64 + j2];
            #pragma unroll
            for (int l = 0; l < LPB; l++) {
                const float4 gg = *(const float4*)&sg[l * GDIM + k];
                acc[l][0] = fmaf(gg.x, w0.x, acc[l][0]);
                acc[l][1] = fmaf(gg.x, w0.y, acc[l][1]);
                acc[l][0] = fmaf(gg.y, w1.x, acc[l][0]);
                acc[l][1] = fmaf(gg.y, w1.y, acc[l][1]);
                acc[l][0] = fmaf(gg.z, w2.x, acc[l][0]);
                acc[l][1] = fmaf(gg.z, w2.y, acc[l][1]);
                acc[l][0] = fmaf(gg.w, w3.x, acc[l][0]);
                acc[l][1] = fmaf(gg.w, w3.y, acc[l][1]);
            }
        }
        #pragma unroll
        for (int l = 0; l < LPB; l++)
            *(float2*)&red[q * 512 + l * 64 + j2] = make_float2(acc[l][0], acc[l][1]);
    }
    __syncthreads();

    // ---- reduce W1 partials + bias + relu -> sh1 ----
    #pragma unroll
    for (int rep = 0; rep < 2; rep++) {
        int p = rep * NTHR + t;
        int l = p >> 6, j = p & 63;
        float s = 0.f;
        #pragma unroll
        for (int q = 0; q < 8; q++) s += red[q * 512 + l * 64 + j];
        sh1[l * 64 + j] = fmaxf(s + b1[j], 0.f);
    }
    __syncthreads();

    // ---- W2: h1[64] @ W2[64,32] + relu (LPB*32 == NTHR) ----
    {
        int j = t & 31, l = t >> 5;
        float a = 0.f;
        #pragma unroll 4
        for (int k = 0; k < 64; k += 4) {
            float w0 = W2[(k    ) * 32 + j];
            float w1 = W2[(k + 1) * 32 + j];
            float w2 = W2[(k + 2) * 32 + j];
            float w3 = W2[(k + 3) * 32 + j];
            const float4 h = *(const float4*)&sh1[l * 64 + k];
            a = fmaf(h.x, w0, a);
            a = fmaf(h.y, w1, a);
            a = fmaf(h.z, w2, a);
            a = fmaf(h.w, w3, a);
        }
        sh2[l * 32 + j] = fmaxf(a + b2[j], 0.f);
    }
    __syncthreads();

    // ---- W3: h2[32] @ W3[32,1] -> out[b] (8 warps, 1 link each) ----
    {
        int w = t >> 5, lane = t & 31;
        float v = sh2[w * 32 + lane] * W3[lane];
        #pragma unroll
        for (int off = 16; off > 0; off >>= 1)
            v += __shfl_xor_sync(0xFFFFFFFFu, v, off);
        if (lane == 0 && (b0 + w) < B)
            out[b0 + w] = v + b3[0];
    }
}

extern "C" void kernel_launch(void* const* d_in, const int* in_sizes, int n_in,
                              void* d_out, int out_size)
{
    const float* flat     = (const float*)d_in[0];
    const float* feat     = (const float*)d_in[1];
    const int*   head_idx = (const int*)  d_in[2];
    const int*   rel_idx  = (const int*)  d_in[3];
    const int*   tail_idx = (const int*)  d_in[4];
    const int*   dist_idx = (const int*)  d_in[5];
    const int*   inter    = (const int*)  d_in[6];
    const float* rel_emb  = (const float*)d_in[7];
    const float* dist_emb = (const float*)d_in[8];
    const float* headW    = (const float*)d_in[9];
    const float* headb    = (const float*)d_in[10];
    const float* tailW    = (const float*)d_in[11];
    const float* tailb    = (const float*)d_in[12];
    const float* W1       = (const float*)d_in[13];
    const float* b1       = (const float*)d_in[14];
    const float* W2       = (const float*)d_in[15];
    const float* b2       = (const float*)d_in[16];
    const float* W3       = (const float*)d_in[17];
    const float* b3       = (const float*)d_in[18];

    int B = in_sizes[2];   // head_idx element count

    cudaFuncSetAttribute(gcw_fused, cudaFuncAttributeMaxDynamicSharedMemorySize, SMEM_BYTES);

    int grid = (B + LPB - 1) / LPB;
    gcw_fused<<<grid, NTHR, SMEM_BYTES>>>(
        flat, feat, head_idx, rel_idx, tail_idx, dist_idx, inter,
        rel_emb, dist_emb, headW, headb, tailW, tailb,
        W1, b1, W2, b2, W3, b3,
        (float*)d_out, B);
}

// round 5
// speedup vs baseline: 1.1668x; 1.1668x over previous
#include <cuda_runtime.h>
#include <cuda_bf16.h>
#include <math.h>

// Problem constants (fixed by the reference)
#define NPSD   256          // L*D = flat node repr dim
#define SINT   32           // intersection set size
#define RELD_  32
#define INPF   32           // node_feat dim
#define DD     64           // dist emb dim
#define GDIM   864          // g_rep dim: 256+256+32+256+32+32

#define LPB    8            // links per block
#define NTHR   256

// shared layout (floats):
//  sg    : LPB*GDIM = 6912
//  sdist : LPB*64   = 512
//  sh1   : LPB*64   = 512
//  sh2   : LPB*32   = 256
//  red   : 8*8*64   = 4096   (red[q*512 + l*64 + j]) - reused pred then W1
//  ints  : sidx LPB*S=256, shead/stail/srel/sdi 4*LPB=32
#define SMEM_FLOATS (LPB*GDIM + LPB*64 + LPB*64 + LPB*32 + 8*LPB*64)
#define SMEM_INTS   (LPB*SINT + 4*LPB)
#define SMEM_BYTES  ((SMEM_FLOATS + SMEM_INTS) * 4)

__global__ void __launch_bounds__(NTHR, 3) gcw_fused(
    const float* __restrict__ flat,      // [N, 256]
    const float* __restrict__ feat,      // [N, 32]
    const int*   __restrict__ head_idx,  // [B]
    const int*   __restrict__ rel_idx,   // [B]
    const int*   __restrict__ tail_idx,  // [B]
    const int*   __restrict__ dist_idx,  // [B]
    const int*   __restrict__ inter,     // [B, 32]
    const float* __restrict__ rel_emb,   // [200, 32]
    const float* __restrict__ dist_emb,  // [11, 64]
    const float* __restrict__ headW,     // [320, 32]
    const float* __restrict__ headb,     // [32]
    const float* __restrict__ tailW,     // [320, 32]
    const float* __restrict__ tailb,     // [32]
    const float* __restrict__ W1,        // [864, 64]
    const float* __restrict__ b1,        // [64]
    const float* __restrict__ W2,        // [64, 32]
    const float* __restrict__ b2,        // [32]
    const float* __restrict__ W3,        // [32, 1]
    const float* __restrict__ b3,        // [1]
    float* __restrict__ out, int B)
{
    extern __shared__ float sh[];
    float* sg    = sh;                          // [LPB][GDIM]
    float* sdist = sg    + LPB * GDIM;          // [LPB][64]
    float* sh1   = sdist + LPB * 64;            // [LPB][64]
    float* sh2   = sh1   + LPB * 64;            // [LPB][32]
    float* red   = sh2   + LPB * 32;            // [8][LPB][64]
    int*   sidx  = (int*)(red + 8 * LPB * 64);  // [LPB][S]
    int*   shead = sidx  + LPB * SINT;
    int*   stail = shead + LPB;
    int*   srel  = stail + LPB;
    int*   sdi   = srel  + LPB;

    const int t  = threadIdx.x;
    const int b0 = blockIdx.x * LPB;

    // ---- load per-link indices ----
    if (t < LPB) {
        int b = min(b0 + t, B - 1);
        shead[t] = head_idx[b];
        stail[t] = tail_idx[b];
        srel[t]  = rel_idx[b];
        sdi[t]   = dist_idx[b];
    }
    {
        int gi = min(b0 * SINT + t, B * SINT - 1);   // LPB*SINT == NTHR
        sidx[t] = inter[gi];
    }
    __syncthreads();

    const int g  = t >> 6;          // 0..3
    const int c4 = (t & 63) * 4;    // float4 column base within 256

    // ---- gather head/tail reprs (float4, streaming: no L1 reuse) ----
    #pragma unroll
    for (int li = 0; li < 2; li++) {
        int l = g + li * 4;
        float4 h  = __ldcs((const float4*)&flat[(long)shead[l] * NPSD + c4]);
        float4 tl = __ldcs((const float4*)&flat[(long)stail[l] * NPSD + c4]);
        *(float4*)&sg[l * GDIM + c4]       = h;
        *(float4*)&sg[l * GDIM + 256 + c4] = tl;
    }
    // rel_repr, head/tail feats  (LPB*32 == NTHR)
    {
        int l = t >> 5, j = t & 31;
        sg[l * GDIM + 512 + j] = rel_emb[(long)srel[l] * RELD_ + j];
        sg[l * GDIM + 800 + j] = feat[(long)shead[l] * INPF + j];
        sg[l * GDIM + 832 + j] = feat[(long)stail[l] * INPF + j];
    }
    // dist_repr (LPB*64 = 512 -> 2 reps)
    #pragma unroll
    for (int rep = 0; rep < 2; rep++) {
        int u = rep * NTHR + t;
        int l = u >> 6, j = u & 63;
        sdist[l * 64 + j] = dist_emb[(long)sdi[l] * DD + j];
    }

    // ---- mid: masked-mean gather, float4 per thread, streaming ----
    #pragma unroll
    for (int li = 0; li < 2; li++) {
        int l = g + li * 4;
        float4 a0 = make_float4(0.f, 0.f, 0.f, 0.f);
        float4 a1 = make_float4(0.f, 0.f, 0.f, 0.f);
        int cnt = 0;
        #pragma unroll 4
        for (int s = 0; s < SINT; s += 2) {
            int i0 = sidx[l * SINT + s];
            int i1 = sidx[l * SINT + s + 1];
            int a0i = i0 < 0 ? -i0 : i0;
            int a1i = i1 < 0 ? -i1 : i1;
            float s0 = (float)((i0 > -1) - (i0 < -1));
            float s1 = (float)((i1 > -1) - (i1 < -1));
            cnt += (i0 != -1) + (i1 != -1);
            const float4 v0 = __ldcs((const float4*)&flat[(long)a0i * NPSD + c4]);
            const float4 v1 = __ldcs((const float4*)&flat[(long)a1i * NPSD + c4]);
            a0.x = fmaf(v0.x, s0, a0.x);
            a0.y = fmaf(v0.y, s0, a0.y);
            a0.z = fmaf(v0.z, s0, a0.z);
            a0.w = fmaf(v0.w, s0, a0.w);
            a1.x = fmaf(v1.x, s1, a1.x);
            a1.y = fmaf(v1.y, s1, a1.y);
            a1.z = fmaf(v1.z, s1, a1.z);
            a1.w = fmaf(v1.w, s1, a1.w);
        }
        float inv = 1.f / (float)max(cnt, 1);
        float4 r;
        r.x = (a0.x + a1.x) * inv;
        r.y = (a0.y + a1.y) * inv;
        r.z = (a0.z + a1.z) * inv;
        r.w = (a0.w + a1.w) * inv;
        *(float4*)&sg[l * GDIM + 544 + c4] = r;
    }

    // ---- emit head/tail init feats (LPB*32 == NTHR) ----
    {
        long hf = (long)B + 2L * B * 32;
        long tf = (long)B + 3L * B * 32;
        int l = t >> 5, j = t & 31;
        int b = b0 + l;
        if (b < B) {
            out[hf + (long)b * 32 + j] = feat[(long)shead[l] * INPF + j];
            out[tf + (long)b * 32 + j] = feat[(long)stail[l] * INPF + j];
        }
    }
    __syncthreads();

    // ---- head/tail pred: md[320] @ W[320,32], jtile=2, 8-way split-K ----
    {
        const int jj2 = (t & 15) * 2;        // 0,2,...,30
        const int sel = (t >> 4) & 1;        // 0=head, 1=tail
        const int q   = t >> 5;              // 0..7
        const float* W = sel ? tailW : headW;
        float acc[LPB][2];
        #pragma unroll
        for (int l = 0; l < LPB; l++) { acc[l][0] = 0.f; acc[l][1] = 0.f; }

        const int k0 = q * 40;
        #pragma unroll
        for (int kk = 0; kk < 40; kk += 4) {
            const int k = k0 + kk;
            float2 w0 = *(const float2*)&W[(k    ) * INPF + jj2];
            float2 w1 = *(const float2*)&W[(k + 1) * INPF + jj2];
            float2 w2 = *(const float2*)&W[(k + 2) * INPF + jj2];
            float2 w3 = *(const float2*)&W[(k + 3) * INPF + jj2];
            #pragma unroll
            for (int l = 0; l < LPB; l++) {
                float4 m;
                if (k < 256) m = *(const float4*)&sg[l * GDIM + 544 + k];
                else         m = *(const float4*)&sdist[l * 64 + (k - 256)];
                acc[l][0] = fmaf(m.x, w0.x, acc[l][0]);
                acc[l][1] = fmaf(m.x, w0.y, acc[l][1]);
                acc[l][0] = fmaf(m.y, w1.x, acc[l][0]);
                acc[l][1] = fmaf(m.y, w1.y, acc[l][1]);
                acc[l][0] = fmaf(m.z, w2.x, acc[l][0]);
                acc[l][1] = fmaf(m.z, w2.y, acc[l][1]);
                acc[l][0] = fmaf(m.w, w3.x, acc[l][0]);
                acc[l][1] = fmaf(m.w, w3.y, acc[l][1]);
            }
        }
        #pragma unroll
        for (int l = 0; l < LPB; l++)
            *(float2*)&red[q * 512 + l * 64 + sel * 32 + jj2] =
                make_float2(acc[l][0], acc[l][1]);
    }
    __syncthreads();

    // ---- reduce pred partials + bias -> out ----
    #pragma unroll
    for (int rep = 0; rep < 2; rep++) {
        int p = rep * NTHR + t;
        int l = p >> 6, j = p & 63, jj = j & 31;
        float s = 0.f;
        #pragma unroll
        for (int q = 0; q < 8; q++) s += red[q * 512 + l * 64 + j];
        int b = b0 + l;
        if (b < B) {
            if (j < 32) out[B + (long)b * 32 + jj] = s + headb[jj];
            else        out[B + (long)B * 32 + (long)b * 32 + jj] = s + tailb[jj];
        }
    }
    __syncthreads();   // red reused below

    // ---- W1: g_rep[864] @ W1[864,64], jtile=2, 8-way split-K ----
    {
        const int j2 = (t & 31) * 2;         // 0,2,...,62
        const int q  = t >> 5;               // 0..7
        float acc[LPB][2];
        #pragma unroll
        for (int l = 0; l < LPB; l++) { acc[l][0] = 0.f; acc[l][1] = 0.f; }

        const int k0 = q * 108;
        #pragma unroll 3
        for (int k = k0; k < k0 + 108; k += 4) {
            float2 w0 = *(const float2*)&W1[(k    ) * 64 + j2];
            float2 w1 = *(const float2*)&W1[(k + 1) * 64 + j2];
            float2 w2 = *(const float2*)&W1[(k + 2) * 64 + j2];
            float2 w3 = *(const float2*)&W1[(k + 3) * 64 + j2];
            #pragma unroll
            for (int l = 0; l < LPB; l++) {
                const float4 gg = *(const float4*)&sg[l * GDIM + k];
                acc[l][0] = fmaf(gg.x, w0.x, acc[l][0]);
                acc[l][1] = fmaf(gg.x, w0.y, acc[l][1]);
                acc[l][0] = fmaf(gg.y, w1.x, acc[l][0]);
                acc[l][1] = fmaf(gg.y, w1.y, acc[l][1]);
                acc[l][0] = fmaf(gg.z, w2.x, acc[l][0]);
                acc[l][1] = fmaf(gg.z, w2.y, acc[l][1]);
                acc[l][0] = fmaf(gg.w, w3.x, acc[l][0]);
                acc[l][1] = fmaf(gg.w, w3.y, acc[l][1]);
            }
        }
        #pragma unroll
        for (int l = 0; l < LPB; l++)
            *(float2*)&red[q * 512 + l * 64 + j2] = make_float2(acc[l][0], acc[l][1]);
    }
    __syncthreads();

    // ---- reduce W1 partials + bias + relu -> sh1 ----
    #pragma unroll
    for (int rep = 0; rep < 2; rep++) {
        int p = rep * NTHR + t;
        int l = p >> 6, j = p & 63;
        float s = 0.f;
        #pragma unroll
        for (int q = 0; q < 8; q++) s += red[q * 512 + l * 64 + j];
        sh1[l * 64 + j] = fmaxf(s + b1[j], 0.f);
    }
    __syncthreads();

    // ---- W2: h1[64] @ W2[64,32] + relu (LPB*32 == NTHR) ----
    {
        int j = t & 31, l = t >> 5;
        float a = 0.f;
        #pragma unroll
        for (int k = 0; k < 64; k += 4) {
            float w0 = W2[(k    ) * 32 + j];
            float w1 = W2[(k + 1) * 32 + j];
            float w2 = W2[(k + 2) * 32 + j];
            float w3 = W2[(k + 3) * 32 + j];
            const float4 h = *(const float4*)&sh1[l * 64 + k];
            a = fmaf(h.x, w0, a);
            a = fmaf(h.y, w1, a);
            a = fmaf(h.z, w2, a);
            a = fmaf(h.w, w3, a);
        }
        sh2[l * 32 + j] = fmaxf(a + b2[j], 0.f);
    }
    __syncthreads();

    // ---- W3: h2[32] @ W3[32,1] -> out[b] (8 warps, 1 link each) ----
    {
        int w = t >> 5, lane = t & 31;
        float v = sh2[w * 32 + lane] * W3[lane];
        #pragma unroll
        for (int off = 16; off > 0; off >>= 1)
            v += __shfl_xor_sync(0xFFFFFFFFu, v, off);
        if (lane == 0 && (b0 + w) < B)
            out[b0 + w] = v + b3[0];
    }
}

extern "C" void kernel_launch(void* const* d_in, const int* in_sizes, int n_in,
                              void* d_out, int out_size)
{
    const float* flat     = (const float*)d_in[0];
    const float* feat     = (const float*)d_in[1];
    const int*   head_idx = (const int*)  d_in[2];
    const int*   rel_idx  = (const int*)  d_in[3];
    const int*   tail_idx = (const int*)  d_in[4];
    const int*   dist_idx = (const int*)  d_in[5];
    const int*   inter    = (const int*)  d_in[6];
    const float* rel_emb  = (const float*)d_in[7];
    const float* dist_emb = (const float*)d_in[8];
    const float* headW    = (const float*)d_in[9];
    const float* headb    = (const float*)d_in[10];
    const float* tailW    = (const float*)d_in[11];
    const float* tailb    = (const float*)d_in[12];
    const float* W1       = (const float*)d_in[13];
    const float* b1       = (const float*)d_in[14];
    const float* W2       = (const float*)d_in[15];
    const float* b2       = (const float*)d_in[16];
    const float* W3       = (const float*)d_in[17];
    const float* b3       = (const float*)d_in[18];

    int B = in_sizes[2];   // head_idx element count

    cudaFuncSetAttribute(gcw_fused, cudaFuncAttributeMaxDynamicSharedMemorySize, SMEM_BYTES);

    int grid = (B + LPB - 1) / LPB;
    gcw_fused<<<grid, NTHR, SMEM_BYTES>>>(
        flat, feat, head_idx, rel_idx, tail_idx, dist_idx, inter,
        rel_emb, dist_emb, headW, headb, tailW, tailb,
        W1, b1, W2, b2, W3, b3,
        (float*)d_out, B);
}

// round 6
// speedup vs baseline: 1.1874x; 1.0177x over previous
#include <cuda_runtime.h>
#include <cuda_bf16.h>
#include <math.h>

// Problem constants (fixed by the reference)
#define NPSD   256          // L*D = flat node repr dim
#define SINT   32           // intersection set size
#define RELD_  32
#define INPF   32           // node_feat dim
#define DD     64           // dist emb dim
#define GDIM   864          // g_rep dim: 256+256+32+256+32+32

#define LPB    8            // links per block
#define NTHR   256

// shared layout (floats):
//  sg    : LPB*GDIM = 6912
//  sdist : LPB*64   = 512
//  sh1   : LPB*64   = 512
//  sh2   : LPB*32   = 256
//  red   : 8*8*64   = 4096   (red[q*512 + l*64 + j]) - reused pred then W1
//  spack : LPB*S int2 = 512 ints
//  shead/stail/srel/sdi : 4*LPB = 32 ints
#define SMEM_FLOATS (LPB*GDIM + LPB*64 + LPB*64 + LPB*32 + 8*LPB*64)
#define SMEM_INTS   (LPB*SINT*2 + 4*LPB)
#define SMEM_BYTES  ((SMEM_FLOATS + SMEM_INTS) * 4)

__global__ void __launch_bounds__(NTHR, 3) gcw_fused(
    const float* __restrict__ flat,      // [N, 256]
    const float* __restrict__ feat,      // [N, 32]
    const int*   __restrict__ head_idx,  // [B]
    const int*   __restrict__ rel_idx,   // [B]
    const int*   __restrict__ tail_idx,  // [B]
    const int*   __restrict__ dist_idx,  // [B]
    const int*   __restrict__ inter,     // [B, 32]
    const float* __restrict__ rel_emb,   // [200, 32]
    const float* __restrict__ dist_emb,  // [11, 64]
    const float* __restrict__ headW,     // [320, 32]
    const float* __restrict__ headb,     // [32]
    const float* __restrict__ tailW,     // [320, 32]
    const float* __restrict__ tailb,     // [32]
    const float* __restrict__ W1,        // [864, 64]
    const float* __restrict__ b1,        // [64]
    const float* __restrict__ W2,        // [64, 32]
    const float* __restrict__ b2,        // [32]
    const float* __restrict__ W3,        // [32, 1]
    const float* __restrict__ b3,        // [1]
    float* __restrict__ out, int B)
{
    extern __shared__ float sh[];
    float* sg    = sh;                          // [LPB][GDIM]
    float* sdist = sg    + LPB * GDIM;          // [LPB][64]
    float* sh1   = sdist + LPB * 64;            // [LPB][64]
    float* sh2   = sh1   + LPB * 64;            // [LPB][32]
    float* red   = sh2   + LPB * 32;            // [8][LPB][64]
    int2*  spack = (int2*)(red + 8 * LPB * 64); // [LPB][S] (row_off, weight)
    int*   shead = (int*)(spack + LPB * SINT);
    int*   stail = shead + LPB;
    int*   srel  = stail + LPB;
    int*   sdi   = srel  + LPB;

    const int t  = threadIdx.x;
    const int b0 = blockIdx.x * LPB;

    // ---- load per-link indices ----
    if (t < LPB) {
        int b = min(b0 + t, B - 1);
        shead[t] = head_idx[b];
        stail[t] = tail_idx[b];
        srel[t]  = rel_idx[b];
        sdi[t]   = dist_idx[b];
    }
    // ---- precompute gather descriptors: warp w <-> link l ----
    {
        int gi = min(b0 * SINT + t, B * SINT - 1);   // LPB*SINT == NTHR
        int c  = inter[gi];
        unsigned m = __ballot_sync(0xFFFFFFFFu, c != -1);
        float inv = 1.f / (float)max(__popc(m), 1);
        float w = (float)((c > -1) - (c < -1)) * inv;    // sign(c+1)/cnt
        spack[t] = make_int2((c < 0 ? -c : c) * NPSD, __float_as_int(w));
    }
    __syncthreads();

    const int g  = t >> 6;          // 0..3
    const int c4 = (t & 63) * 4;    // float4 column base within 256
    const float* flatc4 = flat + c4;

    // ---- gather head/tail reprs (float4, streaming: no L1 reuse) ----
    #pragma unroll
    for (int li = 0; li < 2; li++) {
        int l = g + li * 4;
        float4 h  = __ldcs((const float4*)&flat[(long)shead[l] * NPSD + c4]);
        float4 tl = __ldcs((const float4*)&flat[(long)stail[l] * NPSD + c4]);
        *(float4*)&sg[l * GDIM + c4]       = h;
        *(float4*)&sg[l * GDIM + 256 + c4] = tl;
    }
    // rel_repr, head/tail feats  (LPB*32 == NTHR)
    {
        int l = t >> 5, j = t & 31;
        sg[l * GDIM + 512 + j] = rel_emb[(long)srel[l] * RELD_ + j];
        sg[l * GDIM + 800 + j] = feat[(long)shead[l] * INPF + j];
        sg[l * GDIM + 832 + j] = feat[(long)stail[l] * INPF + j];
    }
    // dist_repr (LPB*64 = 512 -> 2 reps)
    #pragma unroll
    for (int rep = 0; rep < 2; rep++) {
        int u = rep * NTHR + t;
        int l = u >> 6, j = u & 63;
        sdist[l * 64 + j] = dist_emb[(long)sdi[l] * DD + j];
    }

    // ---- mid: weighted gather-sum (weights pre-folded with 1/cnt) ----
    #pragma unroll
    for (int li = 0; li < 2; li++) {
        int l = g + li * 4;
        const int2* spk = spack + l * SINT;
        float4 a0 = make_float4(0.f, 0.f, 0.f, 0.f);
        float4 a1 = make_float4(0.f, 0.f, 0.f, 0.f);
        #pragma unroll 4
        for (int s = 0; s < SINT; s += 2) {
            int2 p0 = spk[s];
            int2 p1 = spk[s + 1];
            const float4 v0 = __ldcs((const float4*)(flatc4 + p0.x));
            const float4 v1 = __ldcs((const float4*)(flatc4 + p1.x));
            float w0 = __int_as_float(p0.y);
            float w1 = __int_as_float(p1.y);
            a0.x = fmaf(v0.x, w0, a0.x);
            a0.y = fmaf(v0.y, w0, a0.y);
            a0.z = fmaf(v0.z, w0, a0.z);
            a0.w = fmaf(v0.w, w0, a0.w);
            a1.x = fmaf(v1.x, w1, a1.x);
            a1.y = fmaf(v1.y, w1, a1.y);
            a1.z = fmaf(v1.z, w1, a1.z);
            a1.w = fmaf(v1.w, w1, a1.w);
        }
        float4 r;
        r.x = a0.x + a1.x;
        r.y = a0.y + a1.y;
        r.z = a0.z + a1.z;
        r.w = a0.w + a1.w;
        *(float4*)&sg[l * GDIM + 544 + c4] = r;
    }
    __syncthreads();

    // ---- emit head/tail init feats from smem (LPB*32 == NTHR) ----
    {
        long hf = (long)B + 2L * B * 32;
        long tf = (long)B + 3L * B * 32;
        int l = t >> 5, j = t & 31;
        int b = b0 + l;
        if (b < B) {
            out[hf + (long)b * 32 + j] = sg[l * GDIM + 800 + j];
            out[tf + (long)b * 32 + j] = sg[l * GDIM + 832 + j];
        }
    }

    // ---- head/tail pred: md[320] @ W[320,32], jtile=2, 8-way split-K ----
    {
        const int jj2 = (t & 15) * 2;        // 0,2,...,30
        const int sel = (t >> 4) & 1;        // 0=head, 1=tail
        const int q   = t >> 5;              // 0..7
        const float* W = sel ? tailW : headW;
        float acc[LPB][2];
        #pragma unroll
        for (int l = 0; l < LPB; l++) { acc[l][0] = 0.f; acc[l][1] = 0.f; }

        const int k0 = q * 40;
        #pragma unroll
        for (int kk = 0; kk < 40; kk += 4) {
            const int k = k0 + kk;
            float2 w0 = *(const float2*)&W[(k    ) * INPF + jj2];
            float2 w1 = *(const float2*)&W[(k + 1) * INPF + jj2];
            float2 w2 = *(const float2*)&W[(k + 2) * INPF + jj2];
            float2 w3 = *(const float2*)&W[(k + 3) * INPF + jj2];
            #pragma unroll
            for (int l = 0; l < LPB; l++) {
                float4 m;
                if (k < 256) m = *(const float4*)&sg[l * GDIM + 544 + k];
                else         m = *(const float4*)&sdist[l * 64 + (k - 256)];
                acc[l][0] = fmaf(m.x, w0.x, acc[l][0]);
                acc[l][1] = fmaf(m.x, w0.y, acc[l][1]);
                acc[l][0] = fmaf(m.y, w1.x, acc[l][0]);
                acc[l][1] = fmaf(m.y, w1.y, acc[l][1]);
                acc[l][0] = fmaf(m.z, w2.x, acc[l][0]);
                acc[l][1] = fmaf(m.z, w2.y, acc[l][1]);
                acc[l][0] = fmaf(m.w, w3.x, acc[l][0]);
                acc[l][1] = fmaf(m.w, w3.y, acc[l][1]);
            }
        }
        #pragma unroll
        for (int l = 0; l < LPB; l++)
            *(float2*)&red[q * 512 + l * 64 + sel * 32 + jj2] =
                make_float2(acc[l][0], acc[l][1]);
    }
    __syncthreads();

    // ---- reduce pred partials + bias -> out ----
    #pragma unroll
    for (int rep = 0; rep < 2; rep++) {
        int p = rep * NTHR + t;
        int l = p >> 6, j = p & 63, jj = j & 31;
        float s = 0.f;
        #pragma unroll
        for (int q = 0; q < 8; q++) s += red[q * 512 + l * 64 + j];
        int b = b0 + l;
        if (b < B) {
            if (j < 32) out[B + (long)b * 32 + jj] = s + headb[jj];
            else        out[B + (long)B * 32 + (long)b * 32 + jj] = s + tailb[jj];
        }
    }
    __syncthreads();   // red reused below

    // ---- W1: g_rep[864] @ W1[864,64], jtile=2, 8-way split-K ----
    {
        const int j2 = (t & 31) * 2;         // 0,2,...,62
        const int q  = t >> 5;               // 0..7
        float acc[LPB][2];
        #pragma unroll
        for (int l = 0; l < LPB; l++) { acc[l][0] = 0.f; acc[l][1] = 0.f; }

        const int k0 = q * 108;
        #pragma unroll 3
        for (int k = k0; k < k0 + 108; k += 4) {
            float2 w0 = *(const float2*)&W1[(k    ) * 64 + j2];
            float2 w1 = *(const float2*)&W1[(k + 1) * 64 + j2];
            float2 w2 = *(const float2*)&W1[(k + 2) * 64 + j2];
            float2 w3 = *(const float2*)&W1[(k + 3) * 64 + j2];
            #pragma unroll
            for (int l = 0; l < LPB; l++) {
                const float4 gg = *(const float4*)&sg[l * GDIM + k];
                acc[l][0] = fmaf(gg.x, w0.x, acc[l][0]);
                acc[l][1] = fmaf(gg.x, w0.y, acc[l][1]);
                acc[l][0] = fmaf(gg.y, w1.x, acc[l][0]);
                acc[l][1] = fmaf(gg.y, w1.y, acc[l][1]);
                acc[l][0] = fmaf(gg.z, w2.x, acc[l][0]);
                acc[l][1] = fmaf(gg.z, w2.y, acc[l][1]);
                acc[l][0] = fmaf(gg.w, w3.x, acc[l][0]);
                acc[l][1] = fmaf(gg.w, w3.y, acc[l][1]);
            }
        }
        #pragma unroll
        for (int l = 0; l < LPB; l++)
            *(float2*)&red[q * 512 + l * 64 + j2] = make_float2(acc[l][0], acc[l][1]);
    }
    __syncthreads();

    // ---- reduce W1 partials + bias + relu -> sh1 ----
    #pragma unroll
    for (int rep = 0; rep < 2; rep++) {
        int p = rep * NTHR + t;
        int l = p >> 6, j = p & 63;
        float s = 0.f;
        #pragma unroll
        for (int q = 0; q < 8; q++) s += red[q * 512 + l * 64 + j];
        sh1[l * 64 + j] = fmaxf(s + b1[j], 0.f);
    }
    __syncthreads();

    // ---- W2: h1[64] @ W2[64,32] + relu (LPB*32 == NTHR) ----
    {
        int j = t & 31, l = t >> 5;
        float a = 0.f;
        #pragma unroll
        for (int k = 0; k < 64; k += 4) {
            float w0 = W2[(k    ) * 32 + j];
            float w1 = W2[(k + 1) * 32 + j];
            float w2 = W2[(k + 2) * 32 + j];
            float w3 = W2[(k + 3) * 32 + j];
            const float4 h = *(const float4*)&sh1[l * 64 + k];
            a = fmaf(h.x, w0, a);
            a = fmaf(h.y, w1, a);
            a = fmaf(h.z, w2, a);
            a = fmaf(h.w, w3, a);
        }
        sh2[l * 32 + j] = fmaxf(a + b2[j], 0.f);
    }
    __syncthreads();

    // ---- W3: h2[32] @ W3[32,1] -> out[b] (8 warps, 1 link each) ----
    {
        int w = t >> 5, lane = t & 31;
        float v = sh2[w * 32 + lane] * W3[lane];
        #pragma unroll
        for (int off = 16; off > 0; off >>= 1)
            v += __shfl_xor_sync(0xFFFFFFFFu, v, off);
        if (lane == 0 && (b0 + w) < B)
            out[b0 + w] = v + b3[0];
    }
}

extern "C" void kernel_launch(void* const* d_in, const int* in_sizes, int n_in,
                              void* d_out, int out_size)
{
    const float* flat     = (const float*)d_in[0];
    const float* feat     = (const float*)d_in[1];
    const int*   head_idx = (const int*)  d_in[2];
    const int*   rel_idx  = (const int*)  d_in[3];
    const int*   tail_idx = (const int*)  d_in[4];
    const int*   dist_idx = (const int*)  d_in[5];
    const int*   inter    = (const int*)  d_in[6];
    const float* rel_emb  = (const float*)d_in[7];
    const float* dist_emb = (const float*)d_in[8];
    const float* headW    = (const float*)d_in[9];
    const float* headb    = (const float*)d_in[10];
    const float* tailW    = (const float*)d_in[11];
    const float* tailb    = (const float*)d_in[12];
    const float* W1       = (const float*)d_in[13];
    const float* b1       = (const float*)d_in[14];
    const float* W2       = (const float*)d_in[15];
    const float* b2       = (const float*)d_in[16];
    const float* W3       = (const float*)d_in[17];
    const float* b3       = (const float*)d_in[18];

    int B = in_sizes[2];   // head_idx element count

    cudaFuncSetAttribute(gcw_fused, cudaFuncAttributeMaxDynamicSharedMemorySize, SMEM_BYTES);

    int grid = (B + LPB - 1) / LPB;
    gcw_fused<<<grid, NTHR, SMEM_BYTES>>>(
        flat, feat, head_idx, rel_idx, tail_idx, dist_idx, inter,
        rel_emb, dist_emb, headW, headb, tailW, tailb,
        W1, b1, W2, b2, W3, b3,
        (float*)d_out, B);
}